// round 1
// baseline (speedup 1.0000x reference)
#include <cuda_runtime.h>
#include <math.h>

#define KT   16
#define NPER 16384
#define DIN  256
#define DOUT 256
#define NTOT (KT * NPER)

// Inverse permutation scratch (alloc-free per harness rules).
__device__ int g_inv[NTOT];

__global__ void build_inv_kernel(const int* __restrict__ perm) {
    int i = blockIdx.x * blockDim.x + threadIdx.x;
    if (i < NTOT) g_inv[perm[i]] = i;
}

// Tiled SGEMM: per CTA computes a 128(M) x 128(N) tile of y[k] = x[k] @ w[k]^T,
// then scatters tanh(rows) to out via the inverse permutation.
// blockDim = 256, micro-tile 8x8 per thread, BK = 16.
__global__ __launch_bounds__(256, 2) void gemm_tanh_scatter(
    const float* __restrict__ x,
    const float* __restrict__ w,
    float* __restrict__ out)
{
    const int k       = blockIdx.z;
    const int rowBase = blockIdx.y * 128;   // M tile (x rows)
    const int colBase = blockIdx.x * 128;   // N tile (output cols / w rows)

    __shared__ float xs[16][128];  // [kk][m]
    __shared__ float ws[16][128];  // [kk][n]

    const int tid = threadIdx.x;
    const int tx  = tid & 15;      // N direction (16 threads * 8 cols = 128)
    const int ty  = tid >> 4;      // M direction (16 threads * 8 rows = 128)

    const float* xk = x + (size_t)k * NPER * DIN;
    const float* wk = w + (size_t)k * DOUT * DIN;

    float acc[8][8];
    #pragma unroll
    for (int i = 0; i < 8; i++)
        #pragma unroll
        for (int j = 0; j < 8; j++)
            acc[i][j] = 0.0f;

    for (int kk0 = 0; kk0 < DIN; kk0 += 16) {
        // Load 128x16 x-tile and 128x16 w-tile, transposed into smem.
        // 512 float4 per tile; 2 per thread each.
        #pragma unroll
        for (int l = 0; l < 2; l++) {
            int idx = tid + l * 256;     // 0..511
            int r   = idx >> 2;          // tile row 0..127
            int c4  = idx & 3;           // which float4 within the 16 cols

            float4 v = *reinterpret_cast<const float4*>(
                xk + (size_t)(rowBase + r) * DIN + kk0 + c4 * 4);
            xs[c4 * 4 + 0][r] = v.x;
            xs[c4 * 4 + 1][r] = v.y;
            xs[c4 * 4 + 2][r] = v.z;
            xs[c4 * 4 + 3][r] = v.w;

            float4 u = *reinterpret_cast<const float4*>(
                wk + (size_t)(colBase + r) * DIN + kk0 + c4 * 4);
            ws[c4 * 4 + 0][r] = u.x;
            ws[c4 * 4 + 1][r] = u.y;
            ws[c4 * 4 + 2][r] = u.z;
            ws[c4 * 4 + 3][r] = u.w;
        }
        __syncthreads();

        #pragma unroll
        for (int kk = 0; kk < 16; kk++) {
            float xr[8], wr[8];
            #pragma unroll
            for (int i = 0; i < 8; i++) xr[i] = xs[kk][ty * 8 + i];
            #pragma unroll
            for (int j = 0; j < 8; j++) wr[j] = ws[kk][tx * 8 + j];
            #pragma unroll
            for (int i = 0; i < 8; i++)
                #pragma unroll
                for (int j = 0; j < 8; j++)
                    acc[i][j] = fmaf(xr[i], wr[j], acc[i][j]);
        }
        __syncthreads();
    }

    // Epilogue: tanh + scatter rows via inverse permutation.
    #pragma unroll
    for (int i = 0; i < 8; i++) {
        int m = rowBase + ty * 8 + i;
        int g = k * NPER + m;          // global neuron index (grouped order)
        int r = g_inv[g];              // destination row in collected order
        float* o = out + (size_t)r * DOUT + colBase + tx * 8;

        float4 v0, v1;
        v0.x = tanhf(acc[i][0]);
        v0.y = tanhf(acc[i][1]);
        v0.z = tanhf(acc[i][2]);
        v0.w = tanhf(acc[i][3]);
        v1.x = tanhf(acc[i][4]);
        v1.y = tanhf(acc[i][5]);
        v1.z = tanhf(acc[i][6]);
        v1.w = tanhf(acc[i][7]);
        *reinterpret_cast<float4*>(o)     = v0;
        *reinterpret_cast<float4*>(o + 4) = v1;
    }
}

extern "C" void kernel_launch(void* const* d_in, const int* in_sizes, int n_in,
                              void* d_out, int out_size)
{
    const float* x    = (const float*)d_in[0];   // [16, 16384, 256] f32
    const float* w    = (const float*)d_in[1];   // [16, 256, 256]   f32
    const int*   perm = (const int*)d_in[2];     // [262144]         i32
    float*       out  = (float*)d_out;           // [262144, 256]    f32

    build_inv_kernel<<<NTOT / 256, 256>>>(perm);

    dim3 grid(DOUT / 128, NPER / 128, KT);       // (2, 128, 16)
    gemm_tanh_scatter<<<grid, 256>>>(x, w, out);
}

// round 3
// speedup vs baseline: 3.2655x; 3.2655x over previous
#include <cuda_runtime.h>
#include <cstdint>
#include <math.h>

#define KT   16
#define NPER 16384
#define DD   256
#define NTOT (KT * NPER)

#define BM 128
#define BN 128
#define BK 32
#define LDS_ROW 36                       // floats per padded smem row
#define TILE_F  (128 * LDS_ROW)          // floats per tile (A or B)
#define BUF_BYTES (2 * TILE_F * 4)       // one stage: A + B
#define SMEM_BYTES (2 * BUF_BYTES)       // 73728 bytes

__device__ int   g_inv[NTOT];
__device__ float g_wr[KT * DD * DD];     // w rounded to nearest tf32

// ---------------------------------------------------------------- prep
__global__ void prep_kernel(const int* __restrict__ perm, const float* __restrict__ w) {
    int i = blockIdx.x * blockDim.x + threadIdx.x;
    if (i < NTOT) g_inv[perm[i]] = i;
    if (i < KT * DD * DD) {
        uint32_t r;
        asm("cvt.rna.tf32.f32 %0, %1;" : "=r"(r) : "f"(w[i]));
        g_wr[i] = __uint_as_float(r);
    }
}

// ---------------------------------------------------------------- helpers
__device__ __forceinline__ uint32_t smem_u32(const void* p) {
    uint32_t a;
    asm("{ .reg .u64 t; cvta.to.shared.u64 t, %1; cvt.u32.u64 %0, t; }" : "=r"(a) : "l"(p));
    return a;
}
__device__ __forceinline__ void cp16(uint32_t sa, const float* ga) {
    asm volatile("cp.async.cg.shared.global [%0], [%1], 16;" :: "r"(sa), "l"(ga));
}
__device__ __forceinline__ void mma_tf32(float* c, const uint32_t* a, const uint32_t* b) {
    asm volatile(
        "mma.sync.aligned.m16n8k8.row.col.f32.tf32.tf32.f32 "
        "{%0,%1,%2,%3}, {%4,%5,%6,%7}, {%8,%9}, {%0,%1,%2,%3};"
        : "+f"(c[0]), "+f"(c[1]), "+f"(c[2]), "+f"(c[3])
        : "r"(a[0]), "r"(a[1]), "r"(a[2]), "r"(a[3]), "r"(b[0]), "r"(b[1]));
}
__device__ __forceinline__ float fast_tanh(float v) {
    v = fminf(9.0f, fmaxf(-9.0f, v));
    float e = __expf(2.0f * v);
    return __fdividef(e - 1.0f, e + 1.0f);
}

__device__ __forceinline__ void issue_slice(uint32_t sb, const float* xg, const float* wg,
                                            int s, int buf, int tid) {
    uint32_t ab = sb + buf * BUF_BYTES;
    uint32_t bb = ab + TILE_F * 4;
    #pragma unroll
    for (int t = 0; t < 4; ++t) {
        int q = tid + t * 256;          // 0..1023
        int m = q >> 3, j = q & 7;
        cp16(ab + m * (LDS_ROW * 4) + j * 16, xg + m * DD + s * BK + j * 4);
    }
    #pragma unroll
    for (int t = 0; t < 4; ++t) {
        int q = tid + t * 256;
        int n = q >> 3, j = q & 7;
        cp16(bb + n * (LDS_ROW * 4) + j * 16, wg + n * DD + s * BK + j * 4);
    }
}

// ---------------------------------------------------------------- main kernel
// 256 threads, warp grid 2(m) x 4(n); warp tile 64x32; mma m16n8k8 tf32.
__global__ __launch_bounds__(256, 2) void gemm_mma_tf32(
    const float* __restrict__ x, float* __restrict__ out)
{
    extern __shared__ float sm[];
    const uint32_t sb = smem_u32(sm);

    const int tid  = threadIdx.x;
    const int lane = tid & 31;
    const int grp  = lane >> 2;      // 0..7
    const int qc   = lane & 3;       // 0..3
    const int wid  = tid >> 5;
    const int wm   = wid >> 2;       // 0..1
    const int wn   = wid & 3;        // 0..3

    const int half = blockIdx.x;     // 0..1  (N half)
    const int mt   = blockIdx.y;     // 0..127 (M tile)
    const int kz   = blockIdx.z;     // 0..15  (type)

    const float* xg = x    + (size_t)kz * NPER * DD + (size_t)mt * 128 * DD;
    const float* wg = g_wr + (size_t)kz * DD * DD   + (size_t)half * 128 * DD;

    float acc[4][4][4];
    #pragma unroll
    for (int i = 0; i < 4; i++)
        #pragma unroll
        for (int j = 0; j < 4; j++)
            #pragma unroll
            for (int q = 0; q < 4; q++)
                acc[i][j][q] = 0.0f;

    // ---------------- pipelined main loop ----------------
    issue_slice(sb, xg, wg, 0, 0, tid);
    asm volatile("cp.async.commit_group;");

    for (int s = 0; s < 8; ++s) {
        if (s < 7) {
            issue_slice(sb, xg, wg, s + 1, (s + 1) & 1, tid);
            asm volatile("cp.async.commit_group;");
            asm volatile("cp.async.wait_group 1;");
        } else {
            asm volatile("cp.async.wait_group 0;");
        }
        __syncthreads();

        const uint32_t* Au = (const uint32_t*)sm + (size_t)(s & 1) * 2 * TILE_F;
        const uint32_t* Bu = Au + TILE_F;

        #pragma unroll
        for (int ks = 0; ks < 4; ++ks) {
            const int k0 = ks * 8 + qc;
            uint32_t a[4][4], b[4][2];
            #pragma unroll
            for (int mb = 0; mb < 4; ++mb) {
                const uint32_t* p = Au + (wm * 64 + mb * 16 + grp) * LDS_ROW + k0;
                a[mb][0] = p[0];
                a[mb][1] = p[8 * LDS_ROW];
                a[mb][2] = p[4];
                a[mb][3] = p[8 * LDS_ROW + 4];
            }
            #pragma unroll
            for (int nb = 0; nb < 4; ++nb) {
                const uint32_t* p = Bu + (wn * 32 + nb * 8 + grp) * LDS_ROW + k0;
                b[nb][0] = p[0];
                b[nb][1] = p[4];
            }
            #pragma unroll
            for (int mb = 0; mb < 4; ++mb)
                #pragma unroll
                for (int nb = 0; nb < 4; ++nb)
                    mma_tf32(acc[mb][nb], a[mb], b[nb]);
        }
        __syncthreads();
    }

    // ---------------- epilogue: tanh + permuted scatter ----------------
    #pragma unroll
    for (int mb = 0; mb < 4; ++mb) {
        int mrow = mt * 128 + wm * 64 + mb * 16 + grp;
        int ra = g_inv[kz * NPER + mrow];
        int rb = g_inv[kz * NPER + mrow + 8];
        #pragma unroll
        for (int nb = 0; nb < 4; ++nb) {
            int col = half * 128 + wn * 32 + nb * 8 + 2 * qc;
            float2 v0, v1;
            v0.x = fast_tanh(acc[mb][nb][0]);
            v0.y = fast_tanh(acc[mb][nb][1]);
            v1.x = fast_tanh(acc[mb][nb][2]);
            v1.y = fast_tanh(acc[mb][nb][3]);
            *reinterpret_cast<float2*>(out + (size_t)ra * DD + col) = v0;
            *reinterpret_cast<float2*>(out + (size_t)rb * DD + col) = v1;
        }
    }
}

// ---------------------------------------------------------------- launch
extern "C" void kernel_launch(void* const* d_in, const int* in_sizes, int n_in,
                              void* d_out, int out_size)
{
    const float* x    = (const float*)d_in[0];
    const float* w    = (const float*)d_in[1];
    const int*   perm = (const int*)d_in[2];
    float*       out  = (float*)d_out;

    cudaFuncSetAttribute(gemm_mma_tf32,
                         cudaFuncAttributeMaxDynamicSharedMemorySize, SMEM_BYTES);

    prep_kernel<<<(KT * DD * DD + 255) / 256, 256>>>(perm, w);

    dim3 grid(2, 128, 16);
    gemm_mma_tf32<<<grid, 256, SMEM_BYTES>>>(x, out);
}

// round 4
// speedup vs baseline: 3.5383x; 1.0836x over previous
#include <cuda_runtime.h>
#include <cstdint>
#include <math.h>

#define KT   16
#define NPER 16384
#define DD   256
#define NTOT (KT * NPER)

#define BK 32
#define LDS_ROW 36                       // floats per padded smem row (144 B)
#define TILE_F  (128 * LDS_ROW)          // floats per tile (A or B)
#define BUF_BYTES (2 * TILE_F * 4)       // one stage: A + B
#define SMEM_BYTES (2 * BUF_BYTES)       // 73728 bytes

__device__ int   g_inv[NTOT];
__device__ float g_wr[KT * DD * DD];     // w rounded to nearest tf32

// ---------------------------------------------------------------- prep
__global__ void prep_kernel(const int* __restrict__ perm, const float* __restrict__ w) {
    int i = blockIdx.x * blockDim.x + threadIdx.x;
    if (i < NTOT) g_inv[perm[i]] = i;
    if (i < KT * DD * DD) {
        uint32_t r;
        asm("cvt.rna.tf32.f32 %0, %1;" : "=r"(r) : "f"(w[i]));
        g_wr[i] = __uint_as_float(r);
    }
}

// ---------------------------------------------------------------- helpers
__device__ __forceinline__ uint32_t smem_u32(const void* p) {
    uint32_t a;
    asm("{ .reg .u64 t; cvta.to.shared.u64 t, %1; cvt.u32.u64 %0, t; }" : "=r"(a) : "l"(p));
    return a;
}
__device__ __forceinline__ void cp16(uint32_t sa, const float* ga) {
    asm volatile("cp.async.cg.shared.global [%0], [%1], 16;" :: "r"(sa), "l"(ga));
}
__device__ __forceinline__ void ldmx4(uint32_t* r, uint32_t addr) {
    asm volatile("ldmatrix.sync.aligned.m8n8.x4.shared.b16 {%0,%1,%2,%3}, [%4];"
                 : "=r"(r[0]), "=r"(r[1]), "=r"(r[2]), "=r"(r[3]) : "r"(addr));
}
__device__ __forceinline__ void mma_tf32(float* c, const uint32_t* a, const uint32_t* b) {
    asm volatile(
        "mma.sync.aligned.m16n8k8.row.col.f32.tf32.tf32.f32 "
        "{%0,%1,%2,%3}, {%4,%5,%6,%7}, {%8,%9}, {%0,%1,%2,%3};"
        : "+f"(c[0]), "+f"(c[1]), "+f"(c[2]), "+f"(c[3])
        : "r"(a[0]), "r"(a[1]), "r"(a[2]), "r"(a[3]), "r"(b[0]), "r"(b[1]));
}
__device__ __forceinline__ float fast_tanh(float v) {
    v = fminf(9.0f, fmaxf(-9.0f, v));
    float e = __expf(2.0f * v);
    return __fdividef(e - 1.0f, e + 1.0f);
}

__device__ __forceinline__ void issue_slice(uint32_t sb, const float* xg, const float* wg,
                                            int s, int buf, int tid) {
    uint32_t ab = sb + buf * BUF_BYTES;
    uint32_t bb = ab + TILE_F * 4;
    #pragma unroll
    for (int t = 0; t < 4; ++t) {
        int q = tid + t * 256;          // 0..1023
        int m = q >> 3, j = q & 7;
        cp16(ab + m * (LDS_ROW * 4) + j * 16, xg + m * DD + s * BK + j * 4);
    }
    #pragma unroll
    for (int t = 0; t < 4; ++t) {
        int q = tid + t * 256;
        int n = q >> 3, j = q & 7;
        cp16(bb + n * (LDS_ROW * 4) + j * 16, wg + n * DD + s * BK + j * 4);
    }
}

// ---------------------------------------------------------------- main kernel
// 256 threads, warp grid 2(m) x 4(n); warp tile 64x32; mma m16n8k8 tf32,
// fragments fed via ldmatrix.x4 (b16 view of tf32).
__global__ __launch_bounds__(256, 2) void gemm_mma_tf32(
    const float* __restrict__ x, float* __restrict__ out)
{
    extern __shared__ float sm[];
    const uint32_t sb = smem_u32(sm);

    const int tid  = threadIdx.x;
    const int lane = tid & 31;
    const int grp  = lane >> 2;      // 0..7
    const int qc   = lane & 3;       // 0..3
    const int wid  = tid >> 5;
    const int wm   = wid >> 2;       // 0..1
    const int wn   = wid & 3;        // 0..3

    const int half = blockIdx.x;     // 0..1  (N half)
    const int mt   = blockIdx.y;     // 0..127 (M tile)
    const int kz   = blockIdx.z;     // 0..15  (type)

    const float* xg = x    + (size_t)kz * NPER * DD + (size_t)mt * 128 * DD;
    const float* wg = g_wr + (size_t)kz * DD * DD   + (size_t)half * 128 * DD;

    // ldmatrix per-lane source rows (constant across slices):
    // A (matrices: M0=(rows+0,k+0) M1=(rows+8,k+0) M2=(rows+0,k+16B) M3=(rows+8,k+16B))
    const int aRow   = wm * 64 + ((lane >> 3) & 1) * 8 + (lane & 7);
    const uint32_t aOffL = (uint32_t)(aRow * (LDS_ROW * 4) + (lane >> 4) * 16);
    // B (M0=(n+0,k0) M1=(n+0,k0+16B) M2=(n+8,k0) M3=(n+8,k0+16B)), per 16-row pair
    const int bRow   = wn * 32 + (lane >> 4) * 8 + (lane & 7);
    const uint32_t bOffL = (uint32_t)(bRow * (LDS_ROW * 4) + ((lane >> 3) & 1) * 16);

    float acc[4][4][4];
    #pragma unroll
    for (int i = 0; i < 4; i++)
        #pragma unroll
        for (int j = 0; j < 4; j++)
            #pragma unroll
            for (int q = 0; q < 4; q++)
                acc[i][j][q] = 0.0f;

    issue_slice(sb, xg, wg, 0, 0, tid);
    asm volatile("cp.async.commit_group;");

    for (int s = 0; s < 8; ++s) {
        if (s < 7) {
            issue_slice(sb, xg, wg, s + 1, (s + 1) & 1, tid);
            asm volatile("cp.async.commit_group;");
            asm volatile("cp.async.wait_group 1;");
        } else {
            asm volatile("cp.async.wait_group 0;");
        }
        __syncthreads();

        const uint32_t aBase = sb + (uint32_t)(s & 1) * BUF_BYTES + aOffL;
        const uint32_t bBase = sb + (uint32_t)(s & 1) * BUF_BYTES + (uint32_t)(TILE_F * 4) + bOffL;

        #pragma unroll
        for (int ks = 0; ks < 4; ++ks) {
            uint32_t a[4][4], b[2][4];
            #pragma unroll
            for (int mb = 0; mb < 4; ++mb)
                ldmx4(a[mb], aBase + mb * (16 * LDS_ROW * 4) + ks * 32);
            #pragma unroll
            for (int pr = 0; pr < 2; ++pr)
                ldmx4(b[pr], bBase + pr * (16 * LDS_ROW * 4) + ks * 32);

            #pragma unroll
            for (int mb = 0; mb < 4; ++mb)
                #pragma unroll
                for (int nb = 0; nb < 4; ++nb)
                    mma_tf32(acc[mb][nb], a[mb], &b[nb >> 1][(nb & 1) * 2]);
        }
        __syncthreads();
    }

    // ---------------- epilogue: tanh + permuted scatter ----------------
    #pragma unroll
    for (int mb = 0; mb < 4; ++mb) {
        int mrow = mt * 128 + wm * 64 + mb * 16 + grp;
        int ra = g_inv[kz * NPER + mrow];
        int rb = g_inv[kz * NPER + mrow + 8];
        #pragma unroll
        for (int nb = 0; nb < 4; ++nb) {
            int col = half * 128 + wn * 32 + nb * 8 + 2 * qc;
            float2 v0, v1;
            v0.x = fast_tanh(acc[mb][nb][0]);
            v0.y = fast_tanh(acc[mb][nb][1]);
            v1.x = fast_tanh(acc[mb][nb][2]);
            v1.y = fast_tanh(acc[mb][nb][3]);
            *reinterpret_cast<float2*>(out + (size_t)ra * DD + col) = v0;
            *reinterpret_cast<float2*>(out + (size_t)rb * DD + col) = v1;
        }
    }
}

// ---------------------------------------------------------------- launch
extern "C" void kernel_launch(void* const* d_in, const int* in_sizes, int n_in,
                              void* d_out, int out_size)
{
    const float* x    = (const float*)d_in[0];
    const float* w    = (const float*)d_in[1];
    const int*   perm = (const int*)d_in[2];
    float*       out  = (float*)d_out;

    cudaFuncSetAttribute(gemm_mma_tf32,
                         cudaFuncAttributeMaxDynamicSharedMemorySize, SMEM_BYTES);

    prep_kernel<<<(KT * DD * DD + 255) / 256, 256>>>(perm, w);

    dim3 grid(2, 128, 16);
    gemm_mma_tf32<<<grid, 256, SMEM_BYTES>>>(x, out);
}

// round 5
// speedup vs baseline: 3.5388x; 1.0001x over previous
#include <cuda_runtime.h>
#include <cstdint>
#include <math.h>

#define KT   16
#define NPER 16384
#define DD   256
#define NTOT (KT * NPER)

#define BK 32
#define NSLICE 8                         // 256 / BK
#define LDS_ROW 36                       // floats per padded smem row (144 B)
#define TILE_F  (128 * LDS_ROW)          // floats per tile (A or B)
#define BUF_BYTES (2 * TILE_F * 4)       // one stage: A + B  (36864 B)
#define NSTAGE 3
#define SMEM_BYTES (NSTAGE * BUF_BYTES)  // 110592 B

__device__ int   g_inv[NTOT];
__device__ float g_wr[KT * DD * DD];     // w rounded to nearest tf32

// ---------------------------------------------------------------- prep
__global__ void prep_kernel(const int* __restrict__ perm, const float* __restrict__ w) {
    int i = blockIdx.x * blockDim.x + threadIdx.x;
    if (i < NTOT) g_inv[perm[i]] = i;
    if (i < KT * DD * DD) {
        uint32_t r;
        asm("cvt.rna.tf32.f32 %0, %1;" : "=r"(r) : "f"(w[i]));
        g_wr[i] = __uint_as_float(r);
    }
}

// ---------------------------------------------------------------- helpers
__device__ __forceinline__ uint32_t smem_u32(const void* p) {
    uint32_t a;
    asm("{ .reg .u64 t; cvta.to.shared.u64 t, %1; cvt.u32.u64 %0, t; }" : "=r"(a) : "l"(p));
    return a;
}
__device__ __forceinline__ void cp16(uint32_t sa, const float* ga) {
    asm volatile("cp.async.cg.shared.global [%0], [%1], 16;" :: "r"(sa), "l"(ga));
}
__device__ __forceinline__ void ldmx4(uint32_t* r, uint32_t addr) {
    asm volatile("ldmatrix.sync.aligned.m8n8.x4.shared.b16 {%0,%1,%2,%3}, [%4];"
                 : "=r"(r[0]), "=r"(r[1]), "=r"(r[2]), "=r"(r[3]) : "r"(addr));
}
__device__ __forceinline__ void mma_tf32(float* c, const uint32_t* a, const uint32_t* b) {
    asm volatile(
        "mma.sync.aligned.m16n8k8.row.col.f32.tf32.tf32.f32 "
        "{%0,%1,%2,%3}, {%4,%5,%6,%7}, {%8,%9}, {%0,%1,%2,%3};"
        : "+f"(c[0]), "+f"(c[1]), "+f"(c[2]), "+f"(c[3])
        : "r"(a[0]), "r"(a[1]), "r"(a[2]), "r"(a[3]), "r"(b[0]), "r"(b[1]));
}
__device__ __forceinline__ float fast_tanh(float v) {
    v = fminf(9.0f, fmaxf(-9.0f, v));
    float e = __expf(2.0f * v);
    return __fdividef(e - 1.0f, e + 1.0f);
}

__device__ __forceinline__ void issue_slice(uint32_t sb, const float* xg, const float* wg,
                                            int s, int buf, int tid) {
    uint32_t ab = sb + buf * BUF_BYTES;
    uint32_t bb = ab + TILE_F * 4;
    #pragma unroll
    for (int t = 0; t < 4; ++t) {
        int q = tid + t * 256;          // 0..1023
        int m = q >> 3, j = q & 7;
        cp16(ab + m * (LDS_ROW * 4) + j * 16, xg + m * DD + s * BK + j * 4);
    }
    #pragma unroll
    for (int t = 0; t < 4; ++t) {
        int q = tid + t * 256;
        int n = q >> 3, j = q & 7;
        cp16(bb + n * (LDS_ROW * 4) + j * 16, wg + n * DD + s * BK + j * 4);
    }
}

// ---------------------------------------------------------------- main kernel
// 256 threads, warp grid 2(m) x 4(n); warp tile 64x32; mma m16n8k8 tf32,
// fragments via ldmatrix.x4 (b16 view), 3-stage cp.async, 1 sync/slice.
__global__ __launch_bounds__(256, 2) void gemm_mma_tf32(
    const float* __restrict__ x, float* __restrict__ out)
{
    extern __shared__ float sm[];
    const uint32_t sb = smem_u32(sm);

    const int tid  = threadIdx.x;
    const int lane = tid & 31;
    const int grp  = lane >> 2;      // 0..7
    const int qc   = lane & 3;       // 0..3
    const int wid  = tid >> 5;
    const int wm   = wid >> 2;       // 0..1
    const int wn   = wid & 3;        // 0..3

    const int half = blockIdx.x;     // 0..1  (N half)
    const int mt   = blockIdx.y;     // 0..127 (M tile)
    const int kz   = blockIdx.z;     // 0..15  (type)

    const float* xg = x    + (size_t)kz * NPER * DD + (size_t)mt * 128 * DD;
    const float* wg = g_wr + (size_t)kz * DD * DD   + (size_t)half * 128 * DD;

    // ldmatrix per-lane source offsets (constant across slices)
    const int aRow   = wm * 64 + ((lane >> 3) & 1) * 8 + (lane & 7);
    const uint32_t aOffL = (uint32_t)(aRow * (LDS_ROW * 4) + (lane >> 4) * 16);
    const int bRow   = wn * 32 + (lane >> 4) * 8 + (lane & 7);
    const uint32_t bOffL = (uint32_t)(bRow * (LDS_ROW * 4) + ((lane >> 3) & 1) * 16);

    float acc[4][4][4];
    #pragma unroll
    for (int i = 0; i < 4; i++)
        #pragma unroll
        for (int j = 0; j < 4; j++)
            #pragma unroll
            for (int q = 0; q < 4; q++)
                acc[i][j][q] = 0.0f;

    issue_slice(sb, xg, wg, 0, 0, tid);
    asm volatile("cp.async.commit_group;");
    issue_slice(sb, xg, wg, 1, 1, tid);
    asm volatile("cp.async.commit_group;");

    int bufC = 0, bufP = 2;   // consume buffer, produce buffer
    for (int s = 0; s < NSLICE; ++s) {
        if (s < NSLICE - 1) asm volatile("cp.async.wait_group 1;");
        else                asm volatile("cp.async.wait_group 0;");
        __syncthreads();

        if (s + 2 < NSLICE) {
            issue_slice(sb, xg, wg, s + 2, bufP, tid);
            asm volatile("cp.async.commit_group;");
        }

        const uint32_t aBase = sb + (uint32_t)bufC * BUF_BYTES + aOffL;
        const uint32_t bBase = aBase + (uint32_t)(TILE_F * 4) - aOffL + bOffL;

        #pragma unroll
        for (int ks = 0; ks < 4; ++ks) {
            uint32_t a[4][4], b[2][4];
            #pragma unroll
            for (int mb = 0; mb < 4; ++mb)
                ldmx4(a[mb], aBase + mb * (16 * LDS_ROW * 4) + ks * 32);
            #pragma unroll
            for (int pr = 0; pr < 2; ++pr)
                ldmx4(b[pr], bBase + pr * (16 * LDS_ROW * 4) + ks * 32);

            #pragma unroll
            for (int mb = 0; mb < 4; ++mb)
                #pragma unroll
                for (int nb = 0; nb < 4; ++nb)
                    mma_tf32(acc[mb][nb], a[mb], &b[nb >> 1][(nb & 1) * 2]);
        }

        bufC = (bufC == 2) ? 0 : bufC + 1;
        bufP = (bufP == 2) ? 0 : bufP + 1;
    }

    // ---------------- epilogue: tanh + permuted scatter ----------------
    #pragma unroll
    for (int mb = 0; mb < 4; ++mb) {
        int mrow = mt * 128 + wm * 64 + mb * 16 + grp;
        int ra = g_inv[kz * NPER + mrow];
        int rb = g_inv[kz * NPER + mrow + 8];
        #pragma unroll
        for (int nb = 0; nb < 4; ++nb) {
            int col = half * 128 + wn * 32 + nb * 8 + 2 * qc;
            float2 v0, v1;
            v0.x = fast_tanh(acc[mb][nb][0]);
            v0.y = fast_tanh(acc[mb][nb][1]);
            v1.x = fast_tanh(acc[mb][nb][2]);
            v1.y = fast_tanh(acc[mb][nb][3]);
            *reinterpret_cast<float2*>(out + (size_t)ra * DD + col) = v0;
            *reinterpret_cast<float2*>(out + (size_t)rb * DD + col) = v1;
        }
    }
}

// ---------------------------------------------------------------- launch
extern "C" void kernel_launch(void* const* d_in, const int* in_sizes, int n_in,
                              void* d_out, int out_size)
{
    const float* x    = (const float*)d_in[0];
    const float* w    = (const float*)d_in[1];
    const int*   perm = (const int*)d_in[2];
    float*       out  = (float*)d_out;

    cudaFuncSetAttribute(gemm_mma_tf32,
                         cudaFuncAttributeMaxDynamicSharedMemorySize, SMEM_BYTES);

    prep_kernel<<<(KT * DD * DD + 255) / 256, 256>>>(perm, w);

    dim3 grid(2, 128, 16);
    gemm_mma_tf32<<<grid, 256, SMEM_BYTES>>>(x, out);
}

// round 6
// speedup vs baseline: 4.0894x; 1.1556x over previous
#include <cuda_runtime.h>
#include <cuda_fp16.h>
#include <cstdint>
#include <math.h>

#define KT   16
#define NPER 16384
#define DD   256
#define NTOT (KT * NPER)

#define BK 32
#define NSLICE 8

// smem layout (bytes), double-buffered stages
#define A32_ROWF   36                    // fp32 staging row: 32 data + 4 pad
#define A32_STAGE  (128 * A32_ROWF * 4)  // 18432
#define A16_ROWH   40                    // fp16 tile row: 32 data + 8 pad (80 B)
#define T16_STAGE  (128 * A16_ROWH * 2)  // 10240
#define A32_OFF    0
#define A16_OFF    (2 * A32_STAGE)                    // 36864
#define B16_OFF    (A16_OFF + 2 * T16_STAGE)          // 57344
#define SMEM_BYTES (B16_OFF + 2 * T16_STAGE)          // 77824

__device__ int    g_inv[NTOT];
__device__ __half g_wh[KT * DD * DD];    // w in fp16

// ---------------------------------------------------------------- prep
__global__ void prep_kernel(const int* __restrict__ perm, const float* __restrict__ w) {
    int i = blockIdx.x * blockDim.x + threadIdx.x;
    if (i < NTOT) g_inv[perm[i]] = i;
    if (i < KT * DD * DD) g_wh[i] = __float2half_rn(w[i]);
}

// ---------------------------------------------------------------- helpers
__device__ __forceinline__ uint32_t smem_u32(const void* p) {
    uint32_t a;
    asm("{ .reg .u64 t; cvta.to.shared.u64 t, %1; cvt.u32.u64 %0, t; }" : "=r"(a) : "l"(p));
    return a;
}
__device__ __forceinline__ void cp16(uint32_t sa, const void* ga) {
    asm volatile("cp.async.cg.shared.global [%0], [%1], 16;" :: "r"(sa), "l"(ga));
}
__device__ __forceinline__ void ldmx4(uint32_t* r, uint32_t addr) {
    asm volatile("ldmatrix.sync.aligned.m8n8.x4.shared.b16 {%0,%1,%2,%3}, [%4];"
                 : "=r"(r[0]), "=r"(r[1]), "=r"(r[2]), "=r"(r[3]) : "r"(addr));
}
__device__ __forceinline__ void mma_f16(float* c, const uint32_t* a, const uint32_t* b) {
    asm volatile(
        "mma.sync.aligned.m16n8k16.row.col.f32.f16.f16.f32 "
        "{%0,%1,%2,%3}, {%4,%5,%6,%7}, {%8,%9}, {%0,%1,%2,%3};"
        : "+f"(c[0]), "+f"(c[1]), "+f"(c[2]), "+f"(c[3])
        : "r"(a[0]), "r"(a[1]), "r"(a[2]), "r"(a[3]), "r"(b[0]), "r"(b[1]));
}
__device__ __forceinline__ float fast_tanh(float v) {
    v = fminf(9.0f, fmaxf(-9.0f, v));
    float e = __expf(2.0f * v);
    return __fdividef(e - 1.0f, e + 1.0f);
}
__device__ __forceinline__ uint32_t h2u(__half2 h) {
    return *reinterpret_cast<uint32_t*>(&h);
}

// cp.async issue for one slice: A fp32 (16 KB) + B fp16 (8 KB)
__device__ __forceinline__ void issue_slice(uint32_t sb, const float* xg,
                                            const __half* wh, int s, int buf, int tid) {
    uint32_t a32 = sb + A32_OFF + buf * A32_STAGE;
    #pragma unroll
    for (int t = 0; t < 4; ++t) {
        int q = tid + t * 256;          // 0..1023
        int m = q >> 3, j = q & 7;
        cp16(a32 + m * (A32_ROWF * 4) + j * 16, xg + m * DD + s * BK + j * 4);
    }
    uint32_t b16 = sb + B16_OFF + buf * T16_STAGE;
    #pragma unroll
    for (int t = 0; t < 2; ++t) {
        int q = tid + t * 256;          // 0..511
        int n = q >> 2, c = q & 3;
        cp16(b16 + n * (A16_ROWH * 2) + c * 16, wh + n * DD + s * BK + c * 8);
    }
}

// ---------------------------------------------------------------- main kernel
// 256 threads, warp grid 2(m) x 4(n); warp tile 64x32; mma m16n8k16 fp16,
// x converted fp32->fp16 in-smem per slice.
__global__ __launch_bounds__(256, 2) void gemm_mma_f16(
    const float* __restrict__ x, float* __restrict__ out)
{
    extern __shared__ char smc[];
    const uint32_t sb = smem_u32(smc);

    const int tid  = threadIdx.x;
    const int lane = tid & 31;
    const int grp  = lane >> 2;      // 0..7
    const int qc   = lane & 3;       // 0..3
    const int wid  = tid >> 5;
    const int wm   = wid >> 2;       // 0..1
    const int wn   = wid & 3;        // 0..3

    const int half = blockIdx.x;     // 0..1  (N half)
    const int mt   = blockIdx.y;     // 0..127 (M tile)
    const int kz   = blockIdx.z;     // 0..15  (type)

    const float*  xg = x    + (size_t)kz * NPER * DD + (size_t)mt * 128 * DD;
    const __half* wh = g_wh + (size_t)kz * DD * DD   + (size_t)half * 128 * DD;

    // ldmatrix per-lane offsets (bytes) — same formulas as verified tf32 layout
    const int aRow = wm * 64 + ((lane >> 3) & 1) * 8 + (lane & 7);
    const uint32_t aOffL = (uint32_t)(aRow * (A16_ROWH * 2) + (lane >> 4) * 16);
    const int bRow = wn * 32 + (lane >> 4) * 8 + (lane & 7);
    const uint32_t bOffL = (uint32_t)(bRow * (A16_ROWH * 2) + ((lane >> 3) & 1) * 16);

    // cvt-phase per-thread coords
    const int cm = tid >> 1;         // row 0..127
    const int ch = tid & 1;          // half of row (16 floats)

    float acc[4][4][4];
    #pragma unroll
    for (int i = 0; i < 4; i++)
        #pragma unroll
        for (int j = 0; j < 4; j++)
            #pragma unroll
            for (int q = 0; q < 4; q++)
                acc[i][j][q] = 0.0f;

    issue_slice(sb, xg, wh, 0, 0, tid);
    asm volatile("cp.async.commit_group;");

    for (int s = 0; s < NSLICE; ++s) {
        asm volatile("cp.async.wait_group 0;");
        __syncthreads();

        // ---- convert A fp32 -> fp16 tile ----
        {
            const float4* src = reinterpret_cast<const float4*>(
                smc + A32_OFF + (s & 1) * A32_STAGE + cm * (A32_ROWF * 4) + ch * 64);
            float4 v0 = src[0], v1 = src[1], v2 = src[2], v3 = src[3];
            uint4 u0, u1;
            u0.x = h2u(__floats2half2_rn(v0.x, v0.y));
            u0.y = h2u(__floats2half2_rn(v0.z, v0.w));
            u0.z = h2u(__floats2half2_rn(v1.x, v1.y));
            u0.w = h2u(__floats2half2_rn(v1.z, v1.w));
            u1.x = h2u(__floats2half2_rn(v2.x, v2.y));
            u1.y = h2u(__floats2half2_rn(v2.z, v2.w));
            u1.z = h2u(__floats2half2_rn(v3.x, v3.y));
            u1.w = h2u(__floats2half2_rn(v3.z, v3.w));
            uint4* dst = reinterpret_cast<uint4*>(
                smc + A16_OFF + (s & 1) * T16_STAGE + cm * (A16_ROWH * 2) + ch * 32);
            dst[0] = u0;
            dst[1] = u1;
        }

        if (s + 1 < NSLICE) {
            issue_slice(sb, xg, wh, s + 1, (s + 1) & 1, tid);
            asm volatile("cp.async.commit_group;");
        }
        __syncthreads();

        // ---- compute: 2 k16-steps ----
        const uint32_t aBase = sb + A16_OFF + (uint32_t)(s & 1) * T16_STAGE + aOffL;
        const uint32_t bBase = sb + B16_OFF + (uint32_t)(s & 1) * T16_STAGE + bOffL;

        #pragma unroll
        for (int ks = 0; ks < 2; ++ks) {
            uint32_t a[4][4], b[2][4];
            #pragma unroll
            for (int mb = 0; mb < 4; ++mb)
                ldmx4(a[mb], aBase + mb * (16 * A16_ROWH * 2) + ks * 32);
            #pragma unroll
            for (int pr = 0; pr < 2; ++pr)
                ldmx4(b[pr], bBase + pr * (16 * A16_ROWH * 2) + ks * 32);

            #pragma unroll
            for (int mb = 0; mb < 4; ++mb)
                #pragma unroll
                for (int nb = 0; nb < 4; ++nb)
                    mma_f16(acc[mb][nb], a[mb], &b[nb >> 1][(nb & 1) * 2]);
        }
    }

    // ---------------- epilogue: tanh + permuted scatter ----------------
    #pragma unroll
    for (int mb = 0; mb < 4; ++mb) {
        int mrow = mt * 128 + wm * 64 + mb * 16 + grp;
        int ra = g_inv[kz * NPER + mrow];
        int rb = g_inv[kz * NPER + mrow + 8];
        #pragma unroll
        for (int nb = 0; nb < 4; ++nb) {
            int col = half * 128 + wn * 32 + nb * 8 + 2 * qc;
            float2 v0, v1;
            v0.x = fast_tanh(acc[mb][nb][0]);
            v0.y = fast_tanh(acc[mb][nb][1]);
            v1.x = fast_tanh(acc[mb][nb][2]);
            v1.y = fast_tanh(acc[mb][nb][3]);
            *reinterpret_cast<float2*>(out + (size_t)ra * DD + col) = v0;
            *reinterpret_cast<float2*>(out + (size_t)rb * DD + col) = v1;
        }
    }
}

// ---------------------------------------------------------------- launch
extern "C" void kernel_launch(void* const* d_in, const int* in_sizes, int n_in,
                              void* d_out, int out_size)
{
    const float* x    = (const float*)d_in[0];
    const float* w    = (const float*)d_in[1];
    const int*   perm = (const int*)d_in[2];
    float*       out  = (float*)d_out;

    cudaFuncSetAttribute(gemm_mma_f16,
                         cudaFuncAttributeMaxDynamicSharedMemorySize, SMEM_BYTES);

    prep_kernel<<<(KT * DD * DD + 255) / 256, 256>>>(perm, w);

    dim3 grid(2, 128, 16);
    gemm_mma_f16<<<grid, 256, SMEM_BYTES>>>(x, out);
}